// round 10
// baseline (speedup 1.0000x reference)
#include <cuda_runtime.h>
#include <cuda_fp16.h>
#include <cstdint>

#define BATCH  8
#define LSEQ   1024
#define DMODEL 512
#define NHEAD  8
#define DKH    64
#define DVH    512
#define MTOT   (BATCH*LSEQ)

// ---------------- scratch (static device globals, zero-initialized) ---------
__device__ __align__(256) __half g_ench[MTOT*DMODEL];
__device__ __align__(256) __half g_Wqh [DMODEL*DMODEL];
__device__ __align__(256) __half g_Wkh [DMODEL*DMODEL];
__device__ __align__(256) __half g_Wvh [NHEAD*DVH*DMODEL];
__device__ __align__(256) __half g_Wgh [NHEAD*DVH*DMODEL];
__device__ __align__(256) __half g_Wfch[DMODEL*DVH];
__device__ __align__(256) __half g_Q [NHEAD*MTOT*DKH];       // [h][m][dk]
__device__ __align__(256) __half g_K [NHEAD*MTOT*DKH];       // [h][m][dk]
__device__ __align__(256) __half g_Vt[NHEAD*BATCH*DVH*LSEQ]; // [h][b][dv][l]
__device__ __align__(256) float  g_S [67108864];             // [hb][q][k] fp32
__device__ __align__(256) __half g_O [NHEAD*MTOT*DVH];       // [h][m][dv]
__device__ __align__(256) __half g_G [NHEAD*MTOT*DVH];
__device__ __align__(256) __half g_Y [MTOT*DVH];
__device__ int   g_len[BATCH];

// ---------------- helpers ----------------------------------------------------
__device__ __forceinline__ uint32_t smem_u32(const void* p) {
    uint32_t a;
    asm("{ .reg .u64 t; cvta.to.shared.u64 t, %1; cvt.u32.u64 %0, t; }"
        : "=r"(a) : "l"(p));
    return a;
}
__device__ __forceinline__ void cp16(uint32_t s, const void* g) {
    asm volatile("cp.async.cg.shared.global [%0], [%1], 16;" :: "r"(s), "l"(g));
}
__device__ __forceinline__ void ldsm4(uint32_t& r0, uint32_t& r1,
                                      uint32_t& r2, uint32_t& r3, uint32_t a) {
    asm volatile("ldmatrix.sync.aligned.m8n8.x4.shared.b16 {%0,%1,%2,%3}, [%4];"
                 : "=r"(r0), "=r"(r1), "=r"(r2), "=r"(r3) : "r"(a));
}
__device__ __forceinline__ void mma_f16(float& c0, float& c1, float& c2, float& c3,
                                        uint32_t a0, uint32_t a1, uint32_t a2, uint32_t a3,
                                        uint32_t b0, uint32_t b1) {
    asm volatile("mma.sync.aligned.m16n8k16.row.col.f32.f16.f16.f32 "
                 "{%0,%1,%2,%3}, {%4,%5,%6,%7}, {%8,%9}, {%0,%1,%2,%3};"
                 : "+f"(c0), "+f"(c1), "+f"(c2), "+f"(c3)
                 : "r"(a0), "r"(a1), "r"(a2), "r"(a3), "r"(b0), "r"(b1));
}

// ---------------- fp32 -> fp16 conversion of enc + weights -------------------
#define N_ENC (MTOT*DMODEL)
#define N_WQ  (DMODEL*DMODEL)
#define N_WV  (NHEAD*DVH*DMODEL)
__global__ void convert_inputs(const float* __restrict__ enc,
                               const float* __restrict__ wq,
                               const float* __restrict__ wk,
                               const float* __restrict__ wv,
                               const float* __restrict__ wg,
                               const float* __restrict__ wfc) {
    const long long i4 = ((long long)blockIdx.x * 256 + threadIdx.x) * 4;
    const float* src; __half* dst; long long off;
    if      (i4 < N_ENC)                   { src = enc; dst = g_ench; off = i4; }
    else if (i4 < N_ENC + N_WQ)            { src = wq;  dst = g_Wqh;  off = i4 - N_ENC; }
    else if (i4 < N_ENC + 2*N_WQ)          { src = wk;  dst = g_Wkh;  off = i4 - N_ENC - N_WQ; }
    else if (i4 < N_ENC + 2*N_WQ + N_WV)   { src = wv;  dst = g_Wvh;  off = i4 - N_ENC - 2*N_WQ; }
    else if (i4 < N_ENC + 2*N_WQ + 2*N_WV) { src = wg;  dst = g_Wgh;  off = i4 - N_ENC - 2*N_WQ - N_WV; }
    else if (i4 < N_ENC + 3*N_WQ + 2*N_WV) { src = wfc; dst = g_Wfch; off = i4 - N_ENC - 2*N_WQ - 2*N_WV; }
    else return;
    const float4 v = *reinterpret_cast<const float4*>(src + off);
    __half2* d2 = reinterpret_cast<__half2*>(dst + off);
    d2[0] = __floats2half2_rn(v.x, v.y);
    d2[1] = __floats2half2_rn(v.z, v.w);
}

// ---------------- mask prep --------------------------------------------------
__global__ void prep_mask(const unsigned char* __restrict__ mask8) {
    __shared__ int s_violate;
    __shared__ int s_len[BATCH];
    const int t = threadIdx.x;
    if (t == 0) s_violate = 0;
    if (t < BATCH) s_len[t] = LSEQ;
    __syncthreads();
    for (int i = t; i < BATCH*LSEQ - 1; i += blockDim.x) {
        if ((i & (LSEQ-1)) != LSEQ-1) {
            if (mask8[i] != 0 && mask8[i+1] == 0) atomicOr(&s_violate, 1);
        }
    }
    __syncthreads();
    const bool is4 = (s_violate != 0);
    if (!is4) {
        for (int i = t; i < BATCH*LSEQ; i += blockDim.x)
            if (mask8[i] != 0) atomicMin(&s_len[i >> 10], i & (LSEQ-1));
    } else {
        const unsigned int* m32 = reinterpret_cast<const unsigned int*>(mask8);
        for (int i = t; i < BATCH*LSEQ; i += blockDim.x)
            if (m32[i] != 0) atomicMin(&s_len[i >> 10], i & (LSEQ-1));
    }
    __syncthreads();
    if (t < BATCH) g_len[t] = s_len[t];
}

// ---------------- fp16 mma GEMM: C = A @ B^T ---------------------------------
#define ASTRH   72
#define ABYTES  (128*ASTRH*2)       // 18432
#define STAGEB  (2*ABYTES)          // 36864
#define SMEM_SZ (3*STAGEB)          // 110592
#define SREG    136

template<int MODE, int SKIP>
__global__ void __launch_bounds__(256, 2)
gemm_mma(const __half* __restrict__ A, long long sA,
         const __half* __restrict__ Bm, long long sB,
         int M, int N, int K,
         void* __restrict__ C, long long sC,
         const float* __restrict__ bias, int sBias,
         const float* __restrict__ resid,
         const __half* B2, const float* bias2, void* C2,
         const __half* B3, const float* bias3, void* C3)
{
    extern __shared__ char dsm[];
    const int tid  = threadIdx.x;
    const int w    = tid >> 5;
    const int lane = tid & 31;
    const int wm   = w & 1;
    const int wn   = w >> 1;
    const int batch = blockIdx.z;
    const int bm = blockIdx.y * 128;

    const __half* Bsrc = Bm;
    const float* biasp = bias;
    void* Cp = C;
    int bn = blockIdx.x * 128;
    int smode = MODE;
    if (MODE == 5) {
        const int bx = blockIdx.x;
        if (bx < 4)      { smode = 0; bn = bx * 128; }
        else if (bx < 8) { smode = 0; bn = (bx-4) * 128; Bsrc = B2; biasp = bias2; Cp = C2; }
        else             { smode = 6; bn = (bx-8) * 128; Bsrc = B3; biasp = bias3; Cp = C3; }
    }

    int Keff = K;
    if (SKIP == 1) {
        if ((bm & (LSEQ-1)) >= g_len[bm >> 10]) return;
    } else if (SKIP == 2) {
        const int L = g_len[batch & (BATCH-1)];
        if (bm >= L || bn >= L) return;
    } else if (SKIP == 4) {
        if ((bm & (LSEQ-1)) >= g_len[bm >> 10]) {
            float* Cf = (float*)Cp;
            const float4 z = {0.f, 0.f, 0.f, 0.f};
            for (int i = tid; i < 128*32; i += 256) {
                const int r = i >> 5, c4 = i & 31;
                *reinterpret_cast<float4*>(&Cf[(long long)(bm + r)*N + bn + c4*4]) = z;
            }
            return;
        }
    }

    const __half* Ab = A    + (long long)batch * sA;
    const __half* Bb = Bsrc + (long long)batch * sB;
    const uint32_t smem0 = smem_u32(dsm);
    const int KC = Keff >> 6;

    auto load_stage = [&](int kc) {
        const int st = kc % 3;
        const uint32_t sa = smem0 + st * STAGEB;
        const uint32_t sb = sa + ABYTES;
        const int k0 = kc << 6;
        #pragma unroll
        for (int i = 0; i < 4; i++) {
            const int idx = tid + i * 256;
            const int row = idx >> 3, chk = idx & 7;
            cp16(sa + row*(ASTRH*2) + chk*16,
                 Ab + (long long)(bm + row) * K + k0 + chk*8);
        }
        #pragma unroll
        for (int i = 0; i < 4; i++) {
            const int idx = tid + i * 256;
            const int row = idx >> 3, chk = idx & 7;
            cp16(sb + row*(ASTRH*2) + chk*16,
                 Bb + (long long)(bn + row) * K + k0 + chk*8);
        }
        asm volatile("cp.async.commit_group;" ::: "memory");
    };

    float acc[4][4][4];
    #pragma unroll
    for (int i = 0; i < 4; i++)
        #pragma unroll
        for (int j = 0; j < 4; j++)
            #pragma unroll
            for (int q = 0; q < 4; q++) acc[i][j][q] = 0.f;

    load_stage(0);
    if (KC > 1) load_stage(1);

    const int lrow_a  = lane & 15;
    const int lkoff_a = (lane >> 4) * 8;
    const int lrow_b  = (lane & 7) + ((lane >> 4) << 3);
    const int lkoff_b = (lane & 8) ? 8 : 0;

    for (int kc = 0; kc < KC; kc++) {
        if (kc + 1 < KC) asm volatile("cp.async.wait_group 1;" ::: "memory");
        else             asm volatile("cp.async.wait_group 0;" ::: "memory");
        __syncthreads();
        if (kc + 2 < KC) load_stage(kc + 2);

        const int st = kc % 3;
        const uint32_t Abase = smem0 + st * STAGEB;
        const uint32_t Bbase = Abase + ABYTES;

        #pragma unroll
        for (int ks = 0; ks < 4; ks++) {
            uint32_t af[4][4];
            #pragma unroll
            for (int mt = 0; mt < 4; mt++) {
                const uint32_t addr = Abase +
                    ((wm*64 + mt*16 + lrow_a)*ASTRH + ks*16 + lkoff_a) * 2;
                ldsm4(af[mt][0], af[mt][1], af[mt][2], af[mt][3], addr);
            }
            uint32_t bf[4][2];
            #pragma unroll
            for (int np = 0; np < 2; np++) {
                const uint32_t addr = Bbase +
                    ((wn*32 + np*16 + lrow_b)*ASTRH + ks*16 + lkoff_b) * 2;
                ldsm4(bf[np*2][0], bf[np*2][1], bf[np*2+1][0], bf[np*2+1][1], addr);
            }
            #pragma unroll
            for (int mt = 0; mt < 4; mt++)
                #pragma unroll
                for (int nt = 0; nt < 4; nt++)
                    mma_f16(acc[mt][nt][0], acc[mt][nt][1], acc[mt][nt][2], acc[mt][nt][3],
                            af[mt][0], af[mt][1], af[mt][2], af[mt][3],
                            bf[nt][0], bf[nt][1]);
        }
    }

    if (MODE == 5 && smode == 6) {   // V transposed store via smem staging
        __syncthreads();
        __half* stg = reinterpret_cast<__half*>(dsm);
        #pragma unroll
        for (int mt = 0; mt < 4; mt++) {
            #pragma unroll
            for (int half_ = 0; half_ < 2; half_++) {
                const int ml = wm*64 + mt*16 + (lane >> 2) + half_*8;
                #pragma unroll
                for (int nt = 0; nt < 4; nt++) {
                    const int nl = wn*32 + nt*8 + (lane & 3)*2;
                    const float2 bv = *reinterpret_cast<const float2*>(&biasp[bn + nl]);
                    stg[nl*SREG + ml]     = __float2half_rn(acc[mt][nt][half_*2 + 0] + bv.x);
                    stg[(nl+1)*SREG + ml] = __float2half_rn(acc[mt][nt][half_*2 + 1] + bv.y);
                }
            }
        }
        __syncthreads();
        const int h = bn >> 9, dv0 = bn & 511;
        const int b = bm >> 10, l0 = bm & (LSEQ-1);
        __half* Vt = (__half*)Cp + (((long long)h*BATCH + b)*DVH + dv0)*LSEQ + l0;
        #pragma unroll
        for (int i = 0; i < 8; i++) {
            const int u = tid + i*256;
            const int dv = u >> 4, lc = u & 15;
            const uint4 o = *reinterpret_cast<const uint4*>(&stg[dv*SREG + lc*8]);
            *reinterpret_cast<uint4*>(&Vt[(long long)dv*LSEQ + lc*8]) = o;
        }
        return;
    }

    #pragma unroll
    for (int mt = 0; mt < 4; mt++) {
        const int r0 = bm + wm*64 + mt*16 + (lane >> 2);
        #pragma unroll
        for (int half_ = 0; half_ < 2; half_++) {
            const int m = r0 + half_*8;
            const int b_idx = m >> 10, l_idx = m & (LSEQ-1);
            #pragma unroll
            for (int nt = 0; nt < 4; nt++) {
                const int n = bn + wn*32 + nt*8 + (lane & 3)*2;
                const float v0 = acc[mt][nt][half_*2 + 0];
                const float v1 = acc[mt][nt][half_*2 + 1];
                if (MODE == 5) {
                    const float2 bv = *reinterpret_cast<const float2*>(&biasp[n]);
                    const int h = n >> 6, d = n & 63;
                    __half* Ch = (__half*)Cp;
                    *reinterpret_cast<__half2*>(&Ch[((long long)h*MTOT + m)*DKH + d]) =
                        __floats2half2_rn(v0 + bv.x, v1 + bv.y);
                } else if (MODE == 2) {
                    float2 o = {v0, v1};
                    *reinterpret_cast<float2*>(
                        &((float*)Cp)[(long long)batch*sC + (long long)m*N + n]) = o;
                } else if (MODE == 3) {
                    const float2 bv = *reinterpret_cast<const float2*>(
                        &biasp[(long long)batch*sBias + n]);
                    __half* Ch = (__half*)Cp;
                    *reinterpret_cast<__half2*>(
                        &Ch[(long long)batch*sC + (long long)m*N + n]) =
                        __floats2half2_rn(v0 + bv.x, v1 + bv.y);
                } else {                  // MODE 4
                    float* Cf = (float*)Cp;
                    float2 o;
                    if (l_idx >= g_len[b_idx]) { o.x = 0.f; o.y = 0.f; }
                    else {
                        const float2 bv = *reinterpret_cast<const float2*>(&biasp[n]);
                        const float2 rv = *reinterpret_cast<const float2*>(
                            &resid[(long long)m*N + n]);
                        o.x = v0 + bv.x + rv.x;
                        o.y = v1 + bv.y + rv.y;
                    }
                    *reinterpret_cast<float2*>(&Cf[(long long)m*N + n]) = o;
                }
            }
        }
    }
}

// ---------------- fused softmax + P@Vt kernel --------------------------------
// Grid (4 dv-chunks, 8 q-tiles, 64 hb). 8 warps, warp = 16 q-rows x 128 dv.
// Reads raw fp32 S tiles from global (L2-shared across dv-chunks), online
// softmax in registers (row stats via 4-lane shfl), in-register fp16 P
// fragments feed mma against 3-stage-buffered Vt smem tiles.
// NOTE: 3 stages required — prefetch distance is 2 (load_v(j+2) while
// iteration j reads buffer j%3); 2 buffers raced (round 9 failure).
#define VSTAGE  18432
#define PV_SMEM (3*VSTAGE)          // 55296

__global__ void __launch_bounds__(256)
pv_softmax(const float* __restrict__ S, const __half* __restrict__ Vt,
           __half* __restrict__ O)
{
    extern __shared__ char dsm[];
    const int tid = threadIdx.x, w = tid >> 5, lane = tid & 31;
    const int hb = blockIdx.z;
    const int L  = g_len[hb & 7];
    const int bm = blockIdx.y * 128;
    if (bm >= L) return;                       // O rows stay 0
    const int dv0 = blockIdx.x * 128;

    const float*  Sg = S  + (long long)hb*LSEQ*LSEQ + (long long)bm*LSEQ;
    const __half* Vg = Vt + (long long)hb*DVH*LSEQ + (long long)dv0*LSEQ;

    const uint32_t sV = smem_u32(dsm);
    const int nkt = (L + 63) >> 6;

    auto load_v = [&](int j) {
        const uint32_t sv = sV + (j % 3)*VSTAGE;
        const int kb = j << 6;
        #pragma unroll
        for (int i = 0; i < 4; i++) {          // 128 dv-rows x 8 chunks of 8h
            const int idx = tid + i*256;
            const int row = idx >> 3, chk = idx & 7;
            cp16(sv + row*144 + chk*16, Vg + (long long)row*LSEQ + kb + chk*8);
        }
        asm volatile("cp.async.commit_group;" ::: "memory");
    };
    load_v(0);
    if (nkt > 1) load_v(1);

    const int r_l = w*16 + (lane >> 2);        // local q-row (and +8)
    const float* Srow0 = Sg + (long long)r_l*LSEQ + (lane & 3)*2;
    const float* Srow1 = Srow0 + 8*LSEQ;

    const int lrow_b  = (lane & 7) + ((lane >> 4) << 3);
    const int lkoff_b = (lane & 8) ? 8 : 0;

    float acc[16][4];
    #pragma unroll
    for (int i = 0; i < 16; i++)
        #pragma unroll
        for (int q = 0; q < 4; q++) acc[i][q] = 0.f;
    float m0 = -1e30f, m1 = -1e30f, l0 = 0.f, l1 = 0.f;
    const float SC = 0.18033688011112042f;     // 0.125 * log2(e)

    for (int j = 0; j < nkt; j++) {
        const int kb = j << 6;
        float s0[8][2], s1[8][2];
        #pragma unroll
        for (int nt = 0; nt < 8; nt++) {
            const float2 a = *reinterpret_cast<const float2*>(Srow0 + kb + nt*8);
            const float2 b = *reinterpret_cast<const float2*>(Srow1 + kb + nt*8);
            s0[nt][0] = a.x; s0[nt][1] = a.y;
            s1[nt][0] = b.x; s1[nt][1] = b.y;
        }
        if (j + 1 < nkt) asm volatile("cp.async.wait_group 1;" ::: "memory");
        else             asm volatile("cp.async.wait_group 0;" ::: "memory");
        __syncthreads();
        if (j + 2 < nkt) load_v(j + 2);        // writes (j+2)%3 != j%3: safe

        const int colb = kb + (lane & 3)*2;
        float rx0 = -1e30f, rx1 = -1e30f;
        #pragma unroll
        for (int nt = 0; nt < 8; nt++) {
            const int c = colb + nt*8;
            s0[nt][0] = (c   < L) ? s0[nt][0]*SC : -1e30f;
            s0[nt][1] = (c+1 < L) ? s0[nt][1]*SC : -1e30f;
            s1[nt][0] = (c   < L) ? s1[nt][0]*SC : -1e30f;
            s1[nt][1] = (c+1 < L) ? s1[nt][1]*SC : -1e30f;
            rx0 = fmaxf(rx0, fmaxf(s0[nt][0], s0[nt][1]));
            rx1 = fmaxf(rx1, fmaxf(s1[nt][0], s1[nt][1]));
        }
        rx0 = fmaxf(rx0, __shfl_xor_sync(~0u, rx0, 1));
        rx0 = fmaxf(rx0, __shfl_xor_sync(~0u, rx0, 2));
        rx1 = fmaxf(rx1, __shfl_xor_sync(~0u, rx1, 1));
        rx1 = fmaxf(rx1, __shfl_xor_sync(~0u, rx1, 2));
        const float mn0 = fmaxf(m0, rx0), mn1 = fmaxf(m1, rx1);
        const float al0 = exp2f(m0 - mn0), al1 = exp2f(m1 - mn1);
        m0 = mn0; m1 = mn1;

        float rs0 = 0.f, rs1 = 0.f;
        uint32_t pf[8][2];
        #pragma unroll
        for (int nt = 0; nt < 8; nt++) {
            const float p00 = exp2f(s0[nt][0] - m0), p01 = exp2f(s0[nt][1] - m0);
            const float p10 = exp2f(s1[nt][0] - m1), p11 = exp2f(s1[nt][1] - m1);
            rs0 += p00 + p01; rs1 += p10 + p11;
            const __half2 h0 = __floats2half2_rn(p00, p01);
            const __half2 h1 = __floats2half2_rn(p10, p11);
            pf[nt][0] = *reinterpret_cast<const uint32_t*>(&h0);
            pf[nt][1] = *reinterpret_cast<const uint32_t*>(&h1);
        }
        rs0 += __shfl_xor_sync(~0u, rs0, 1); rs0 += __shfl_xor_sync(~0u, rs0, 2);
        rs1 += __shfl_xor_sync(~0u, rs1, 1); rs1 += __shfl_xor_sync(~0u, rs1, 2);
        l0 = l0*al0 + rs0; l1 = l1*al1 + rs1;
        #pragma unroll
        for (int nt = 0; nt < 16; nt++) {
            acc[nt][0] *= al0; acc[nt][1] *= al0;
            acc[nt][2] *= al1; acc[nt][3] *= al1;
        }

        const uint32_t sv = sV + (j % 3)*VSTAGE;
        #pragma unroll
        for (int ks = 0; ks < 4; ks++) {
            const uint32_t a0 = pf[2*ks][0],   a1 = pf[2*ks][1];
            const uint32_t a2 = pf[2*ks+1][0], a3 = pf[2*ks+1][1];
            #pragma unroll
            for (int np = 0; np < 8; np++) {
                uint32_t b0, b1, b2, b3;
                ldsm4(b0, b1, b2, b3,
                      sv + ((np*16 + lrow_b)*72 + ks*16 + lkoff_b)*2);
                mma_f16(acc[np*2][0],   acc[np*2][1],   acc[np*2][2],   acc[np*2][3],
                        a0, a1, a2, a3, b0, b1);
                mma_f16(acc[np*2+1][0], acc[np*2+1][1], acc[np*2+1][2], acc[np*2+1][3],
                        a0, a1, a2, a3, b2, b3);
            }
        }
    }

    const float inv0 = 1.f / l0, inv1 = 1.f / l1;
    __half* Ob = O + ((long long)hb*LSEQ + bm + r_l)*DVH + dv0;
    #pragma unroll
    for (int nt = 0; nt < 16; nt++) {
        const int c = nt*8 + (lane & 3)*2;
        *reinterpret_cast<__half2*>(Ob + c) =
            __floats2half2_rn(acc[nt][0]*inv0, acc[nt][1]*inv0);
        *reinterpret_cast<__half2*>(Ob + 8*DVH + c) =
            __floats2half2_rn(acc[nt][2]*inv1, acc[nt][3]*inv1);
    }
}

// ---------------- head-gate softmax + weighted combine (fp16 in/out) ---------
__global__ void gate_combine(const __half* __restrict__ G,
                             const __half* __restrict__ O,
                             __half* __restrict__ Y) {
    const int HS4 = MTOT*DVH/4;
    const int i = blockIdx.x * blockDim.x + threadIdx.x;
    if (i >= HS4) return;
    const int m = i >> 7;
    if ((m & (LSEQ-1)) >= g_len[m >> 10]) return;

    const uint2* G4 = reinterpret_cast<const uint2*>(G);
    const uint2* O4 = reinterpret_cast<const uint2*>(O);
    float g[NHEAD][4];
    float mx0 = -1e30f, mx1 = -1e30f, mx2 = -1e30f, mx3 = -1e30f;
    #pragma unroll
    for (int h = 0; h < NHEAD; h++) {
        const uint2 u = G4[(long long)h*HS4 + i];
        const float2 a = __half22float2(*reinterpret_cast<const __half2*>(&u.x));
        const float2 b = __half22float2(*reinterpret_cast<const __half2*>(&u.y));
        g[h][0] = a.x; g[h][1] = a.y; g[h][2] = b.x; g[h][3] = b.y;
        mx0 = fmaxf(mx0, a.x); mx1 = fmaxf(mx1, a.y);
        mx2 = fmaxf(mx2, b.x); mx3 = fmaxf(mx3, b.y);
    }
    float acc0=0, acc1=0, acc2=0, acc3=0, s0=0, s1=0, s2=0, s3=0;
    #pragma unroll
    for (int h = 0; h < NHEAD; h++) {
        const uint2 u = O4[(long long)h*HS4 + i];
        const float2 a = __half22float2(*reinterpret_cast<const __half2*>(&u.x));
        const float2 b = __half22float2(*reinterpret_cast<const __half2*>(&u.y));
        const float e0 = __expf(g[h][0] - mx0), e1 = __expf(g[h][1] - mx1);
        const float e2 = __expf(g[h][2] - mx2), e3 = __expf(g[h][3] - mx3);
        s0 += e0; s1 += e1; s2 += e2; s3 += e3;
        acc0 += e0*a.x; acc1 += e1*a.y; acc2 += e2*b.x; acc3 += e3*b.y;
    }
    uint2 o;
    *reinterpret_cast<__half2*>(&o.x) = __floats2half2_rn(acc0/s0, acc1/s1);
    *reinterpret_cast<__half2*>(&o.y) = __floats2half2_rn(acc2/s2, acc3/s3);
    reinterpret_cast<uint2*>(Y)[i] = o;
}

// ---------------- launch ------------------------------------------------------
extern "C" void kernel_launch(void* const* d_in, const int* in_sizes, int n_in,
                              void* d_out, int out_size) {
    const float*         enc  = (const float*)d_in[0];
    const unsigned char* npm  = (const unsigned char*)d_in[1];
    const float* w_q  = (const float*)d_in[3];
    const float* b_q  = (const float*)d_in[4];
    const float* w_k  = (const float*)d_in[5];
    const float* b_k  = (const float*)d_in[6];
    const float* w_v  = (const float*)d_in[7];
    const float* b_v  = (const float*)d_in[8];
    const float* w_g  = (const float*)d_in[9];
    const float* b_g  = (const float*)d_in[10];
    const float* w_fc = (const float*)d_in[11];
    const float* b_fc = (const float*)d_in[12];
    float* out = (float*)d_out;

    __half *pEnc,*pWq,*pWk,*pWv,*pWg,*pWfc,*pQ,*pK,*pVt,*pO,*pG,*pY;
    float *pS;
    cudaGetSymbolAddress((void**)&pEnc, g_ench);
    cudaGetSymbolAddress((void**)&pWq,  g_Wqh);
    cudaGetSymbolAddress((void**)&pWk,  g_Wkh);
    cudaGetSymbolAddress((void**)&pWv,  g_Wvh);
    cudaGetSymbolAddress((void**)&pWg,  g_Wgh);
    cudaGetSymbolAddress((void**)&pWfc, g_Wfch);
    cudaGetSymbolAddress((void**)&pQ,   g_Q);
    cudaGetSymbolAddress((void**)&pK,   g_K);
    cudaGetSymbolAddress((void**)&pVt,  g_Vt);
    cudaGetSymbolAddress((void**)&pS,   g_S);
    cudaGetSymbolAddress((void**)&pO,   g_O);
    cudaGetSymbolAddress((void**)&pG,   g_G);
    cudaGetSymbolAddress((void**)&pY,   g_Y);

    cudaFuncSetAttribute(gemm_mma<5,1>, cudaFuncAttributeMaxDynamicSharedMemorySize, SMEM_SZ);
    cudaFuncSetAttribute(gemm_mma<2,2>, cudaFuncAttributeMaxDynamicSharedMemorySize, SMEM_SZ);
    cudaFuncSetAttribute(gemm_mma<3,1>, cudaFuncAttributeMaxDynamicSharedMemorySize, SMEM_SZ);
    cudaFuncSetAttribute(gemm_mma<4,4>, cudaFuncAttributeMaxDynamicSharedMemorySize, SMEM_SZ);
    cudaFuncSetAttribute(pv_softmax,    cudaFuncAttributeMaxDynamicSharedMemorySize, PV_SMEM);

    const int M = MTOT;
    dim3 blk(256);

    convert_inputs<<<(N_ENC + 3*N_WQ + 2*N_WV) / 1024, 256>>>(enc, w_q, w_k, w_v, w_g, w_fc);
    prep_mask<<<1, 256>>>(npm);

    // Fused Q/K/V projections (fp16): Q,K -> [h][m][dk]; V -> Vt[h][b][dv][l]
    gemm_mma<5,1><<<dim3(40, M/128, 1), blk, SMEM_SZ>>>(
        pEnc,0, pWq,0, M, NHEAD*DKH, DMODEL, pQ,0, b_q,0, nullptr,
        pWk, b_k, pK, pWv, b_v, pVt);
    // S = Q @ K^T per (h,b), fp32 out, masked tiles skipped
    gemm_mma<2,2><<<dim3(LSEQ/128, LSEQ/128, NHEAD*BATCH), blk, SMEM_SZ>>>(
        pQ,(long long)LSEQ*DKH, pK,(long long)LSEQ*DKH,
        LSEQ, LSEQ, DKH, pS,(long long)LSEQ*LSEQ, nullptr,0, nullptr,
        nullptr,nullptr,nullptr, nullptr,nullptr,nullptr);
    // O = softmax(S*0.125) @ Vt^T, fused, fp16 out
    pv_softmax<<<dim3(DVH/128, LSEQ/128, NHEAD*BATCH), blk, PV_SMEM>>>(pS, pVt, pO);
    // gate logits: batched over heads, per-head bias, fp16 out
    gemm_mma<3,1><<<dim3(DVH/128, M/128, NHEAD), blk, SMEM_SZ>>>(
        pO,(long long)M*DVH, pWg,(long long)DVH*DMODEL,
        M, DVH, DMODEL, pG,(long long)M*DVH, b_g, DVH, nullptr,
        nullptr,nullptr,nullptr, nullptr,nullptr,nullptr);
    gate_combine<<<(M*DVH/4 + 255)/256, 256>>>(pG, pO, pY);
    // final FC + bias + residual + pad zeroing (fp32 out)
    gemm_mma<4,4><<<dim3(DMODEL/128, M/128, 1), blk, SMEM_SZ>>>(
        pY,0, pWfc,0, M, DMODEL, DVH, out,0, b_fc,0, enc,
        nullptr,nullptr,nullptr, nullptr,nullptr,nullptr);
}

// round 11
// speedup vs baseline: 1.1032x; 1.1032x over previous
#include <cuda_runtime.h>
#include <cuda_fp16.h>
#include <cstdint>

#define BATCH  8
#define LSEQ   1024
#define DMODEL 512
#define NHEAD  8
#define DKH    64
#define DVH    512
#define MTOT   (BATCH*LSEQ)

// ---------------- scratch (static device globals, zero-initialized) ---------
__device__ __align__(256) __half g_ench[MTOT*DMODEL];
__device__ __align__(256) __half g_Wqh [DMODEL*DMODEL];
__device__ __align__(256) __half g_Wkh [DMODEL*DMODEL];
__device__ __align__(256) __half g_Wvh [NHEAD*DVH*DMODEL];
__device__ __align__(256) __half g_Wgh [NHEAD*DVH*DMODEL];
__device__ __align__(256) __half g_Wfch[DMODEL*DVH];
__device__ __align__(256) __half g_Q [NHEAD*MTOT*DKH];       // [h][m][dk]
__device__ __align__(256) __half g_K [NHEAD*MTOT*DKH];       // [h][m][dk]
__device__ __align__(256) __half g_Vt[NHEAD*BATCH*DVH*LSEQ]; // [h][b][dv][l]
__device__ __align__(256) float  g_S [67108864];             // [hb][q][k] fp32
__device__ __align__(256) __half g_P [67108864];             // softmax(S) fp16
__device__ __align__(256) __half g_O [NHEAD*MTOT*DVH];       // [h][m][dv]
__device__ __align__(256) __half g_G [NHEAD*MTOT*DVH];
__device__ __align__(256) __half g_Y [MTOT*DVH];
__device__ int   g_len[BATCH];

// ---------------- helpers ----------------------------------------------------
__device__ __forceinline__ uint32_t smem_u32(const void* p) {
    uint32_t a;
    asm("{ .reg .u64 t; cvta.to.shared.u64 t, %1; cvt.u32.u64 %0, t; }"
        : "=r"(a) : "l"(p));
    return a;
}
__device__ __forceinline__ void cp16(uint32_t s, const void* g) {
    asm volatile("cp.async.cg.shared.global [%0], [%1], 16;" :: "r"(s), "l"(g));
}
__device__ __forceinline__ void ldsm4(uint32_t& r0, uint32_t& r1,
                                      uint32_t& r2, uint32_t& r3, uint32_t a) {
    asm volatile("ldmatrix.sync.aligned.m8n8.x4.shared.b16 {%0,%1,%2,%3}, [%4];"
                 : "=r"(r0), "=r"(r1), "=r"(r2), "=r"(r3) : "r"(a));
}
__device__ __forceinline__ void mma_f16(float& c0, float& c1, float& c2, float& c3,
                                        uint32_t a0, uint32_t a1, uint32_t a2, uint32_t a3,
                                        uint32_t b0, uint32_t b1) {
    asm volatile("mma.sync.aligned.m16n8k16.row.col.f32.f16.f16.f32 "
                 "{%0,%1,%2,%3}, {%4,%5,%6,%7}, {%8,%9}, {%0,%1,%2,%3};"
                 : "+f"(c0), "+f"(c1), "+f"(c2), "+f"(c3)
                 : "r"(a0), "r"(a1), "r"(a2), "r"(a3), "r"(b0), "r"(b1));
}

// ---------------- fp32 -> fp16 conversion of enc + weights -------------------
#define N_ENC (MTOT*DMODEL)
#define N_WQ  (DMODEL*DMODEL)
#define N_WV  (NHEAD*DVH*DMODEL)
__global__ void convert_inputs(const float* __restrict__ enc,
                               const float* __restrict__ wq,
                               const float* __restrict__ wk,
                               const float* __restrict__ wv,
                               const float* __restrict__ wg,
                               const float* __restrict__ wfc) {
    const long long i4 = ((long long)blockIdx.x * 256 + threadIdx.x) * 4;
    const float* src; __half* dst; long long off;
    if      (i4 < N_ENC)                   { src = enc; dst = g_ench; off = i4; }
    else if (i4 < N_ENC + N_WQ)            { src = wq;  dst = g_Wqh;  off = i4 - N_ENC; }
    else if (i4 < N_ENC + 2*N_WQ)          { src = wk;  dst = g_Wkh;  off = i4 - N_ENC - N_WQ; }
    else if (i4 < N_ENC + 2*N_WQ + N_WV)   { src = wv;  dst = g_Wvh;  off = i4 - N_ENC - 2*N_WQ; }
    else if (i4 < N_ENC + 2*N_WQ + 2*N_WV) { src = wg;  dst = g_Wgh;  off = i4 - N_ENC - 2*N_WQ - N_WV; }
    else if (i4 < N_ENC + 3*N_WQ + 2*N_WV) { src = wfc; dst = g_Wfch; off = i4 - N_ENC - 2*N_WQ - 2*N_WV; }
    else return;
    const float4 v = *reinterpret_cast<const float4*>(src + off);
    __half2* d2 = reinterpret_cast<__half2*>(dst + off);
    d2[0] = __floats2half2_rn(v.x, v.y);
    d2[1] = __floats2half2_rn(v.z, v.w);
}

// ---------------- mask prep --------------------------------------------------
__global__ void prep_mask(const unsigned char* __restrict__ mask8) {
    __shared__ int s_violate;
    __shared__ int s_len[BATCH];
    const int t = threadIdx.x;
    if (t == 0) s_violate = 0;
    if (t < BATCH) s_len[t] = LSEQ;
    __syncthreads();
    for (int i = t; i < BATCH*LSEQ - 1; i += blockDim.x) {
        if ((i & (LSEQ-1)) != LSEQ-1) {
            if (mask8[i] != 0 && mask8[i+1] == 0) atomicOr(&s_violate, 1);
        }
    }
    __syncthreads();
    const bool is4 = (s_violate != 0);
    if (!is4) {
        for (int i = t; i < BATCH*LSEQ; i += blockDim.x)
            if (mask8[i] != 0) atomicMin(&s_len[i >> 10], i & (LSEQ-1));
    } else {
        const unsigned int* m32 = reinterpret_cast<const unsigned int*>(mask8);
        for (int i = t; i < BATCH*LSEQ; i += blockDim.x)
            if (m32[i] != 0) atomicMin(&s_len[i >> 10], i & (LSEQ-1));
    }
    __syncthreads();
    if (t < BATCH) g_len[t] = s_len[t];
}

// ---------------- fp16 mma GEMM: C = A @ B^T ---------------------------------
// BM=BN=128, BK=64 halfs, 256 threads, 3-stage cp.async pipeline, ldmatrix.x4.
// ALL epilogues are smem-staged (fp32 tile [128][132]) then written with
// fully-coalesced float4/uint4 stores; bias/residual added in the coalesced
// pass in fp32 (identical math to round 8).
// MODE: 2 fp32 plain batched (S); 7 fp16 plain batched (O);
//       3 fp16 +bias[batch*sBias+n] (gate); 4 fp32 final (+bias+resid,pad0);
//       5 fused QKV (bx<4 Q, <8 K -> fp16 [h][m][dk]; else V -> transposed
//         fp16 Vt[h][b][dv][l] via smem staging)
// SKIP: 1 row-tile skip; 2 S row+col skip; 3 PV row skip + K clamp;
//       4 final zero-fill padded rows.
#define ASTRH   72
#define ABYTES  (128*ASTRH*2)       // 18432
#define STAGEB  (2*ABYTES)          // 36864
#define SMEM_SZ (3*STAGEB)          // 110592
#define SREG    136                 // V transpose staging stride (halfs)
#define ESTR    132                 // epilogue staging stride (floats)

template<int MODE, int SKIP>
__global__ void __launch_bounds__(256, 2)
gemm_mma(const __half* __restrict__ A, long long sA,
         const __half* __restrict__ Bm, long long sB,
         int M, int N, int K,
         void* __restrict__ C, long long sC,
         const float* __restrict__ bias, int sBias,
         const float* __restrict__ resid,
         const __half* B2, const float* bias2, void* C2,
         const __half* B3, const float* bias3, void* C3)
{
    extern __shared__ char dsm[];
    const int tid  = threadIdx.x;
    const int w    = tid >> 5;
    const int lane = tid & 31;
    const int wm   = w & 1;
    const int wn   = w >> 1;
    const int batch = blockIdx.z;
    const int bm = blockIdx.y * 128;

    const __half* Bsrc = Bm;
    const float* biasp = bias;
    void* Cp = C;
    int bn = blockIdx.x * 128;
    int smode = MODE;
    if (MODE == 5) {
        const int bx = blockIdx.x;
        if (bx < 4)      { smode = 0; bn = bx * 128; }
        else if (bx < 8) { smode = 0; bn = (bx-4) * 128; Bsrc = B2; biasp = bias2; Cp = C2; }
        else             { smode = 6; bn = (bx-8) * 128; Bsrc = B3; biasp = bias3; Cp = C3; }
    }

    int Keff = K;
    if (SKIP == 1) {
        if ((bm & (LSEQ-1)) >= g_len[bm >> 10]) return;
    } else if (SKIP == 2) {
        const int L = g_len[batch & (BATCH-1)];
        if (bm >= L || bn >= L) return;
    } else if (SKIP == 3) {
        const int L = g_len[batch & (BATCH-1)];
        if (bm >= L) return;
        Keff = (L + 63) & ~63;
    } else if (SKIP == 4) {
        if ((bm & (LSEQ-1)) >= g_len[bm >> 10]) {
            float* Cf = (float*)Cp;
            const float4 z = {0.f, 0.f, 0.f, 0.f};
            for (int i = tid; i < 128*32; i += 256) {
                const int r = i >> 5, c4 = i & 31;
                *reinterpret_cast<float4*>(&Cf[(long long)(bm + r)*N + bn + c4*4]) = z;
            }
            return;
        }
    }

    const __half* Ab = A    + (long long)batch * sA;
    const __half* Bb = Bsrc + (long long)batch * sB;
    const uint32_t smem0 = smem_u32(dsm);
    const int KC = Keff >> 6;

    auto load_stage = [&](int kc) {
        const int st = kc % 3;
        const uint32_t sa = smem0 + st * STAGEB;
        const uint32_t sb = sa + ABYTES;
        const int k0 = kc << 6;
        #pragma unroll
        for (int i = 0; i < 4; i++) {
            const int idx = tid + i * 256;
            const int row = idx >> 3, chk = idx & 7;
            cp16(sa + row*(ASTRH*2) + chk*16,
                 Ab + (long long)(bm + row) * K + k0 + chk*8);
        }
        #pragma unroll
        for (int i = 0; i < 4; i++) {
            const int idx = tid + i * 256;
            const int row = idx >> 3, chk = idx & 7;
            cp16(sb + row*(ASTRH*2) + chk*16,
                 Bb + (long long)(bn + row) * K + k0 + chk*8);
        }
        asm volatile("cp.async.commit_group;" ::: "memory");
    };

    float acc[4][4][4];
    #pragma unroll
    for (int i = 0; i < 4; i++)
        #pragma unroll
        for (int j = 0; j < 4; j++)
            #pragma unroll
            for (int q = 0; q < 4; q++) acc[i][j][q] = 0.f;

    load_stage(0);
    if (KC > 1) load_stage(1);

    const int lrow_a  = lane & 15;
    const int lkoff_a = (lane >> 4) * 8;
    const int lrow_b  = (lane & 7) + ((lane >> 4) << 3);
    const int lkoff_b = (lane & 8) ? 8 : 0;

    for (int kc = 0; kc < KC; kc++) {
        if (kc + 1 < KC) asm volatile("cp.async.wait_group 1;" ::: "memory");
        else             asm volatile("cp.async.wait_group 0;" ::: "memory");
        __syncthreads();
        if (kc + 2 < KC) load_stage(kc + 2);

        const int st = kc % 3;
        const uint32_t Abase = smem0 + st * STAGEB;
        const uint32_t Bbase = Abase + ABYTES;

        #pragma unroll
        for (int ks = 0; ks < 4; ks++) {
            uint32_t af[4][4];
            #pragma unroll
            for (int mt = 0; mt < 4; mt++) {
                const uint32_t addr = Abase +
                    ((wm*64 + mt*16 + lrow_a)*ASTRH + ks*16 + lkoff_a) * 2;
                ldsm4(af[mt][0], af[mt][1], af[mt][2], af[mt][3], addr);
            }
            uint32_t bf[4][2];
            #pragma unroll
            for (int np = 0; np < 2; np++) {
                const uint32_t addr = Bbase +
                    ((wn*32 + np*16 + lrow_b)*ASTRH + ks*16 + lkoff_b) * 2;
                ldsm4(bf[np*2][0], bf[np*2][1], bf[np*2+1][0], bf[np*2+1][1], addr);
            }
            #pragma unroll
            for (int mt = 0; mt < 4; mt++)
                #pragma unroll
                for (int nt = 0; nt < 4; nt++)
                    mma_f16(acc[mt][nt][0], acc[mt][nt][1], acc[mt][nt][2], acc[mt][nt][3],
                            af[mt][0], af[mt][1], af[mt][2], af[mt][3],
                            bf[nt][0], bf[nt][1]);
        }
    }

    // ---------------- V transposed store via smem staging (smode 6) ----------
    if (MODE == 5 && smode == 6) {
        __syncthreads();
        __half* stg = reinterpret_cast<__half*>(dsm);
        #pragma unroll
        for (int mt = 0; mt < 4; mt++) {
            #pragma unroll
            for (int half_ = 0; half_ < 2; half_++) {
                const int ml = wm*64 + mt*16 + (lane >> 2) + half_*8;
                #pragma unroll
                for (int nt = 0; nt < 4; nt++) {
                    const int nl = wn*32 + nt*8 + (lane & 3)*2;
                    const float2 bv = *reinterpret_cast<const float2*>(&biasp[bn + nl]);
                    stg[nl*SREG + ml]     = __float2half_rn(acc[mt][nt][half_*2 + 0] + bv.x);
                    stg[(nl+1)*SREG + ml] = __float2half_rn(acc[mt][nt][half_*2 + 1] + bv.y);
                }
            }
        }
        __syncthreads();
        const int h = bn >> 9, dv0 = bn & 511;
        const int b = bm >> 10, l0 = bm & (LSEQ-1);
        __half* Vt = (__half*)Cp + (((long long)h*BATCH + b)*DVH + dv0)*LSEQ + l0;
        #pragma unroll
        for (int i = 0; i < 8; i++) {
            const int u = tid + i*256;
            const int dv = u >> 4, lc = u & 15;
            const uint4 o = *reinterpret_cast<const uint4*>(&stg[dv*SREG + lc*8]);
            *reinterpret_cast<uint4*>(&Vt[(long long)dv*LSEQ + lc*8]) = o;
        }
        return;
    }

    // ---------------- staged epilogue (coalesced stores) ---------------------
    __syncthreads();                              // pipeline smem reads done
    float* stg = reinterpret_cast<float*>(dsm);   // [128][ESTR]
    #pragma unroll
    for (int mt = 0; mt < 4; mt++) {
        #pragma unroll
        for (int half_ = 0; half_ < 2; half_++) {
            const int r_l = wm*64 + mt*16 + (lane >> 2) + half_*8;
            #pragma unroll
            for (int nt = 0; nt < 4; nt++) {
                const int c_l = wn*32 + nt*8 + (lane & 3)*2;
                stg[r_l*ESTR + c_l]     = acc[mt][nt][half_*2 + 0];
                stg[r_l*ESTR + c_l + 1] = acc[mt][nt][half_*2 + 1];
            }
        }
    }
    __syncthreads();

    if (MODE == 2) {
        float* Cf = (float*)Cp + (long long)batch*sC + (long long)bm*N + bn;
        #pragma unroll
        for (int i = 0; i < 16; i++) {
            const int idx = tid + i*256;
            const int r = idx >> 5, c = (idx & 31)*4;
            *reinterpret_cast<float4*>(&Cf[(long long)r*N + c]) =
                *reinterpret_cast<const float4*>(&stg[r*ESTR + c]);
        }
    } else if (MODE == 7 || MODE == 3 || MODE == 5) {
        #pragma unroll
        for (int i = 0; i < 8; i++) {
            const int idx = tid + i*256;
            const int r = idx >> 4, c = (idx & 15)*8;
            float4 a = *reinterpret_cast<const float4*>(&stg[r*ESTR + c]);
            float4 b = *reinterpret_cast<const float4*>(&stg[r*ESTR + c + 4]);
            if (MODE == 3) {
                const float* bb = biasp + (long long)batch*sBias + bn + c;
                const float4 b0 = *reinterpret_cast<const float4*>(bb);
                const float4 b1 = *reinterpret_cast<const float4*>(bb + 4);
                a.x += b0.x; a.y += b0.y; a.z += b0.z; a.w += b0.w;
                b.x += b1.x; b.y += b1.y; b.z += b1.z; b.w += b1.w;
            } else if (MODE == 5) {
                const float* bb = biasp + bn + c;
                const float4 b0 = *reinterpret_cast<const float4*>(bb);
                const float4 b1 = *reinterpret_cast<const float4*>(bb + 4);
                a.x += b0.x; a.y += b0.y; a.z += b0.z; a.w += b0.w;
                b.x += b1.x; b.y += b1.y; b.z += b1.z; b.w += b1.w;
            }
            const __half2 h0 = __floats2half2_rn(a.x, a.y);
            const __half2 h1 = __floats2half2_rn(a.z, a.w);
            const __half2 h2 = __floats2half2_rn(b.x, b.y);
            const __half2 h3 = __floats2half2_rn(b.z, b.w);
            uint4 o;
            o.x = *reinterpret_cast<const uint32_t*>(&h0);
            o.y = *reinterpret_cast<const uint32_t*>(&h1);
            o.z = *reinterpret_cast<const uint32_t*>(&h2);
            o.w = *reinterpret_cast<const uint32_t*>(&h3);
            const int m = bm + r;
            __half* Ch;
            if (MODE == 5) {
                const int n0 = bn + c, h = n0 >> 6, d = n0 & 63;
                Ch = (__half*)Cp + ((long long)h*MTOT + m)*DKH + d;
            } else {
                Ch = (__half*)Cp + (long long)batch*sC + (long long)m*N + bn + c;
            }
            *reinterpret_cast<uint4*>(Ch) = o;
        }
    } else {  // MODE 4: fp32 final (+bias+resid, zero padded rows)
        #pragma unroll
        for (int i = 0; i < 16; i++) {
            const int idx = tid + i*256;
            const int r = idx >> 5, c = (idx & 31)*4;
            const int m = bm + r;
            const int b_idx = m >> 10, l_idx = m & (LSEQ-1);
            float4 o;
            if (l_idx >= g_len[b_idx]) { o.x = o.y = o.z = o.w = 0.f; }
            else {
                const float4 v  = *reinterpret_cast<const float4*>(&stg[r*ESTR + c]);
                const float4 bv = *reinterpret_cast<const float4*>(&biasp[bn + c]);
                const float4 rv = *reinterpret_cast<const float4*>(
                    &resid[(long long)m*N + bn + c]);
                o.x = v.x + bv.x + rv.x;
                o.y = v.y + bv.y + rv.y;
                o.z = v.z + bv.z + rv.z;
                o.w = v.w + bv.w + rv.w;
            }
            *reinterpret_cast<float4*>(&((float*)Cp)[(long long)m*N + bn + c]) = o;
        }
    }
}

// ---------------- masked row softmax: fp32 in (S), fp16 out (P) --------------
__global__ void softmax_rows(const float* __restrict__ S, __half* __restrict__ P) {
    const int hb  = blockIdx.y;
    const int len = g_len[hb & (BATCH-1)];
    const int q   = blockIdx.x;
    if (q >= len) return;                  // padded rows: P stays 0 (zero-init)
    const float4* row = reinterpret_cast<const float4*>(
        S + ((long long)hb * LSEQ + q) * LSEQ);
    __half2* prow = reinterpret_cast<__half2*>(
        P + ((long long)hb * LSEQ + q) * LSEQ);

    const int t = threadIdx.x;
    const float4 v = row[t];
    const int j0 = t * 4;
    const float NEG = -1e30f;
    float x0 = (j0+0 < len) ? v.x : NEG;
    float x1 = (j0+1 < len) ? v.y : NEG;
    float x2 = (j0+2 < len) ? v.z : NEG;
    float x3 = (j0+3 < len) ? v.w : NEG;

    __shared__ float rmax[8], rsum[8];
    float mx = fmaxf(fmaxf(x0, x1), fmaxf(x2, x3));
    #pragma unroll
    for (int o = 16; o; o >>= 1) mx = fmaxf(mx, __shfl_xor_sync(~0u, mx, o));
    if ((t & 31) == 0) rmax[t >> 5] = mx;
    __syncthreads();
    mx = rmax[0];
    #pragma unroll
    for (int i = 1; i < 8; i++) mx = fmaxf(mx, rmax[i]);
    mx *= 0.125f;

    const float e0 = __expf(x0*0.125f - mx);
    const float e1 = __expf(x1*0.125f - mx);
    const float e2 = __expf(x2*0.125f - mx);
    const float e3 = __expf(x3*0.125f - mx);
    float s = e0 + e1 + e2 + e3;
    #pragma unroll
    for (int o = 16; o; o >>= 1) s += __shfl_xor_sync(~0u, s, o);
    if ((t & 31) == 0) rsum[t >> 5] = s;
    __syncthreads();
    s = rsum[0];
    #pragma unroll
    for (int i = 1; i < 8; i++) s += rsum[i];
    const float inv = 1.f / s;

    prow[t*2]   = __floats2half2_rn(e0*inv, e1*inv);
    prow[t*2+1] = __floats2half2_rn(e2*inv, e3*inv);
}

// ---------------- head-gate softmax + weighted combine (fp16 in/out) ---------
__global__ void gate_combine(const __half* __restrict__ G,
                             const __half* __restrict__ O,
                             __half* __restrict__ Y) {
    const int HS4 = MTOT*DVH/4;
    const int i = blockIdx.x * blockDim.x + threadIdx.x;
    if (i >= HS4) return;
    const int m = i >> 7;
    if ((m & (LSEQ-1)) >= g_len[m >> 10]) return;

    const uint2* G4 = reinterpret_cast<const uint2*>(G);
    const uint2* O4 = reinterpret_cast<const uint2*>(O);
    float g[NHEAD][4];
    float mx0 = -1e30f, mx1 = -1e30f, mx2 = -1e30f, mx3 = -1e30f;
    #pragma unroll
    for (int h = 0; h < NHEAD; h++) {
        const uint2 u = G4[(long long)h*HS4 + i];
        const float2 a = __half22float2(*reinterpret_cast<const __half2*>(&u.x));
        const float2 b = __half22float2(*reinterpret_cast<const __half2*>(&u.y));
        g[h][0] = a.x; g[h][1] = a.y; g[h][2] = b.x; g[h][3] = b.y;
        mx0 = fmaxf(mx0, a.x); mx1 = fmaxf(mx1, a.y);
        mx2 = fmaxf(mx2, b.x); mx3 = fmaxf(mx3, b.y);
    }
    float acc0=0, acc1=0, acc2=0, acc3=0, s0=0, s1=0, s2=0, s3=0;
    #pragma unroll
    for (int h = 0; h < NHEAD; h++) {
        const uint2 u = O4[(long long)h*HS4 + i];
        const float2 a = __half22float2(*reinterpret_cast<const __half2*>(&u.x));
        const float2 b = __half22float2(*reinterpret_cast<const __half2*>(&u.y));
        const float e0 = __expf(g[h][0] - mx0), e1 = __expf(g[h][1] - mx1);
        const float e2 = __expf(g[h][2] - mx2), e3 = __expf(g[h][3] - mx3);
        s0 += e0; s1 += e1; s2 += e2; s3 += e3;
        acc0 += e0*a.x; acc1 += e1*a.y; acc2 += e2*b.x; acc3 += e3*b.y;
    }
    uint2 o;
    *reinterpret_cast<__half2*>(&o.x) = __floats2half2_rn(acc0/s0, acc1/s1);
    *reinterpret_cast<__half2*>(&o.y) = __floats2half2_rn(acc2/s2, acc3/s3);
    reinterpret_cast<uint2*>(Y)[i] = o;
}

// ---------------- launch ------------------------------------------------------
extern "C" void kernel_launch(void* const* d_in, const int* in_sizes, int n_in,
                              void* d_out, int out_size) {
    const float*         enc  = (const float*)d_in[0];
    const unsigned char* npm  = (const unsigned char*)d_in[1];
    const float* w_q  = (const float*)d_in[3];
    const float* b_q  = (const float*)d_in[4];
    const float* w_k  = (const float*)d_in[5];
    const float* b_k  = (const float*)d_in[6];
    const float* w_v  = (const float*)d_in[7];
    const float* b_v  = (const float*)d_in[8];
    const float* w_g  = (const float*)d_in[9];
    const float* b_g  = (const float*)d_in[10];
    const float* w_fc = (const float*)d_in[11];
    const float* b_fc = (const float*)d_in[12];
    float* out = (float*)d_out;

    __half *pEnc,*pWq,*pWk,*pWv,*pWg,*pWfc,*pQ,*pK,*pVt,*pP,*pO,*pG,*pY;
    float *pS;
    cudaGetSymbolAddress((void**)&pEnc, g_ench);
    cudaGetSymbolAddress((void**)&pWq,  g_Wqh);
    cudaGetSymbolAddress((void**)&pWk,  g_Wkh);
    cudaGetSymbolAddress((void**)&pWv,  g_Wvh);
    cudaGetSymbolAddress((void**)&pWg,  g_Wgh);
    cudaGetSymbolAddress((void**)&pWfc, g_Wfch);
    cudaGetSymbolAddress((void**)&pQ,   g_Q);
    cudaGetSymbolAddress((void**)&pK,   g_K);
    cudaGetSymbolAddress((void**)&pVt,  g_Vt);
    cudaGetSymbolAddress((void**)&pS,   g_S);
    cudaGetSymbolAddress((void**)&pP,   g_P);
    cudaGetSymbolAddress((void**)&pO,   g_O);
    cudaGetSymbolAddress((void**)&pG,   g_G);
    cudaGetSymbolAddress((void**)&pY,   g_Y);

    cudaFuncSetAttribute(gemm_mma<5,1>, cudaFuncAttributeMaxDynamicSharedMemorySize, SMEM_SZ);
    cudaFuncSetAttribute(gemm_mma<2,2>, cudaFuncAttributeMaxDynamicSharedMemorySize, SMEM_SZ);
    cudaFuncSetAttribute(gemm_mma<7,3>, cudaFuncAttributeMaxDynamicSharedMemorySize, SMEM_SZ);
    cudaFuncSetAttribute(gemm_mma<3,1>, cudaFuncAttributeMaxDynamicSharedMemorySize, SMEM_SZ);
    cudaFuncSetAttribute(gemm_mma<4,4>, cudaFuncAttributeMaxDynamicSharedMemorySize, SMEM_SZ);

    const int M = MTOT;
    dim3 blk(256);

    convert_inputs<<<(N_ENC + 3*N_WQ + 2*N_WV) / 1024, 256>>>(enc, w_q, w_k, w_v, w_g, w_fc);
    prep_mask<<<1, 256>>>(npm);

    // Fused Q/K/V projections (fp16): Q,K -> [h][m][dk]; V -> Vt[h][b][dv][l]
    gemm_mma<5,1><<<dim3(40, M/128, 1), blk, SMEM_SZ>>>(
        pEnc,0, pWq,0, M, NHEAD*DKH, DMODEL, pQ,0, b_q,0, nullptr,
        pWk, b_k, pK, pWv, b_v, pVt);
    // S = Q @ K^T per (h,b), fp32 out, masked tiles skipped
    gemm_mma<2,2><<<dim3(LSEQ/128, LSEQ/128, NHEAD*BATCH), blk, SMEM_SZ>>>(
        pQ,(long long)LSEQ*DKH, pK,(long long)LSEQ*DKH,
        LSEQ, LSEQ, DKH, pS,(long long)LSEQ*LSEQ, nullptr,0, nullptr,
        nullptr,nullptr,nullptr, nullptr,nullptr,nullptr);
    softmax_rows<<<dim3(LSEQ, NHEAD*BATCH), 256>>>(pS, pP);
    // O = P @ Vt^T per (h,b), fp16 out, K clamped to len
    gemm_mma<7,3><<<dim3(DVH/128, LSEQ/128, NHEAD*BATCH), blk, SMEM_SZ>>>(
        pP,(long long)LSEQ*LSEQ, pVt,(long long)DVH*LSEQ,
        LSEQ, DVH, LSEQ, pO,(long long)LSEQ*DVH, nullptr,0, nullptr,
        nullptr,nullptr,nullptr, nullptr,nullptr,nullptr);
    // gate logits: batched over heads, per-head bias, fp16 out
    gemm_mma<3,1><<<dim3(DVH/128, M/128, NHEAD), blk, SMEM_SZ>>>(
        pO,(long long)M*DVH, pWg,(long long)DVH*DMODEL,
        M, DVH, DMODEL, pG,(long long)M*DVH, b_g, DVH, nullptr,
        nullptr,nullptr,nullptr, nullptr,nullptr,nullptr);
    gate_combine<<<(M*DVH/4 + 255)/256, 256>>>(pG, pO, pY);
    // final FC + bias + residual + pad zeroing (fp32 out)
    gemm_mma<4,4><<<dim3(DMODEL/128, M/128, 1), blk, SMEM_SZ>>>(
        pY,0, pWfc,0, M, DMODEL, DVH, out,0, b_fc,0, enc,
        nullptr,nullptr,nullptr, nullptr,nullptr,nullptr);
}

// round 12
// speedup vs baseline: 1.1497x; 1.0421x over previous
#include <cuda_runtime.h>
#include <cuda_fp16.h>
#include <cstdint>

#define BATCH  8
#define LSEQ   1024
#define DMODEL 512
#define NHEAD  8
#define DKH    64
#define DVH    512
#define MTOT   (BATCH*LSEQ)

// ---------------- scratch (static device globals, zero-initialized) ---------
// Padded regions (rows/cols >= len[b]) are never written and stay 0.
__device__ __align__(256) __half g_ench[MTOT*DMODEL];
__device__ __align__(256) __half g_Wqh [DMODEL*DMODEL];
__device__ __align__(256) __half g_Wkh [DMODEL*DMODEL];
__device__ __align__(256) __half g_Wvh [NHEAD*DVH*DMODEL];
__device__ __align__(256) __half g_Wgh [NHEAD*DVH*DMODEL];
__device__ __align__(256) __half g_Wfch[DMODEL*DVH];
__device__ __align__(256) __half g_Q [NHEAD*MTOT*DKH];       // [h][m][dk]
__device__ __align__(256) __half g_K [NHEAD*MTOT*DKH];       // [h][m][dk]
__device__ __align__(256) __half g_Vt[NHEAD*BATCH*DVH*LSEQ]; // [h][b][dv][l]
__device__ __align__(256) __half g_S [67108864];             // [hb][q][k] fp16
__device__ __align__(256) __half g_P [67108864];             // softmax(S) fp16
__device__ __align__(256) __half g_O [NHEAD*MTOT*DVH];       // [h][m][dv]
__device__ __align__(256) __half g_G [NHEAD*MTOT*DVH];
__device__ __align__(256) __half g_Y [MTOT*DVH];
__device__ int   g_len[BATCH];

// ---------------- helpers ----------------------------------------------------
__device__ __forceinline__ uint32_t smem_u32(const void* p) {
    uint32_t a;
    asm("{ .reg .u64 t; cvta.to.shared.u64 t, %1; cvt.u32.u64 %0, t; }"
        : "=r"(a) : "l"(p));
    return a;
}
__device__ __forceinline__ void cp16(uint32_t s, const void* g) {
    asm volatile("cp.async.cg.shared.global [%0], [%1], 16;" :: "r"(s), "l"(g));
}
__device__ __forceinline__ void ldsm4(uint32_t& r0, uint32_t& r1,
                                      uint32_t& r2, uint32_t& r3, uint32_t a) {
    asm volatile("ldmatrix.sync.aligned.m8n8.x4.shared.b16 {%0,%1,%2,%3}, [%4];"
                 : "=r"(r0), "=r"(r1), "=r"(r2), "=r"(r3) : "r"(a));
}
__device__ __forceinline__ void mma_f16(float& c0, float& c1, float& c2, float& c3,
                                        uint32_t a0, uint32_t a1, uint32_t a2, uint32_t a3,
                                        uint32_t b0, uint32_t b1) {
    asm volatile("mma.sync.aligned.m16n8k16.row.col.f32.f16.f16.f32 "
                 "{%0,%1,%2,%3}, {%4,%5,%6,%7}, {%8,%9}, {%0,%1,%2,%3};"
                 : "+f"(c0), "+f"(c1), "+f"(c2), "+f"(c3)
                 : "r"(a0), "r"(a1), "r"(a2), "r"(a3), "r"(b0), "r"(b1));
}

// ---------------- fp32 -> fp16 conversion of enc + weights -------------------
#define N_ENC (MTOT*DMODEL)
#define N_WQ  (DMODEL*DMODEL)
#define N_WV  (NHEAD*DVH*DMODEL)
__global__ void convert_inputs(const float* __restrict__ enc,
                               const float* __restrict__ wq,
                               const float* __restrict__ wk,
                               const float* __restrict__ wv,
                               const float* __restrict__ wg,
                               const float* __restrict__ wfc) {
    const long long i4 = ((long long)blockIdx.x * 256 + threadIdx.x) * 4;
    const float* src; __half* dst; long long off;
    if      (i4 < N_ENC)                   { src = enc; dst = g_ench; off = i4; }
    else if (i4 < N_ENC + N_WQ)            { src = wq;  dst = g_Wqh;  off = i4 - N_ENC; }
    else if (i4 < N_ENC + 2*N_WQ)          { src = wk;  dst = g_Wkh;  off = i4 - N_ENC - N_WQ; }
    else if (i4 < N_ENC + 2*N_WQ + N_WV)   { src = wv;  dst = g_Wvh;  off = i4 - N_ENC - 2*N_WQ; }
    else if (i4 < N_ENC + 2*N_WQ + 2*N_WV) { src = wg;  dst = g_Wgh;  off = i4 - N_ENC - 2*N_WQ - N_WV; }
    else if (i4 < N_ENC + 3*N_WQ + 2*N_WV) { src = wfc; dst = g_Wfch; off = i4 - N_ENC - 2*N_WQ - 2*N_WV; }
    else return;
    const float4 v = *reinterpret_cast<const float4*>(src + off);
    __half2* d2 = reinterpret_cast<__half2*>(dst + off);
    d2[0] = __floats2half2_rn(v.x, v.y);
    d2[1] = __floats2half2_rn(v.z, v.w);
}

// ---------------- mask prep --------------------------------------------------
__global__ void prep_mask(const unsigned char* __restrict__ mask8) {
    __shared__ int s_violate;
    __shared__ int s_len[BATCH];
    const int t = threadIdx.x;
    if (t == 0) s_violate = 0;
    if (t < BATCH) s_len[t] = LSEQ;
    __syncthreads();
    for (int i = t; i < BATCH*LSEQ - 1; i += blockDim.x) {
        if ((i & (LSEQ-1)) != LSEQ-1) {
            if (mask8[i] != 0 && mask8[i+1] == 0) atomicOr(&s_violate, 1);
        }
    }
    __syncthreads();
    const bool is4 = (s_violate != 0);
    if (!is4) {
        for (int i = t; i < BATCH*LSEQ; i += blockDim.x)
            if (mask8[i] != 0) atomicMin(&s_len[i >> 10], i & (LSEQ-1));
    } else {
        const unsigned int* m32 = reinterpret_cast<const unsigned int*>(mask8);
        for (int i = t; i < BATCH*LSEQ; i += blockDim.x)
            if (m32[i] != 0) atomicMin(&s_len[i >> 10], i & (LSEQ-1));
    }
    __syncthreads();
    if (t < BATCH) g_len[t] = s_len[t];
}

// ---------------- fp16 mma GEMM: C = A @ B^T ---------------------------------
// BM=BN=128, BK=64 halfs, 256 threads, 3-stage cp.async pipeline, ldmatrix.x4,
// round-8 direct epilogue stores (staged variant regressed in round 11).
// MODE: 7 fp16 plain batched (S, O); 3 fp16 +bias[batch*sBias+n] (gate);
//       4 fp32 final (+bias+resid, pad0); 5 fused QKV (bx<4 Q, <8 K -> fp16
//       [h][m][dk]; else V -> transposed fp16 Vt[h][b][dv][l] via smem staging)
// SKIP: 1 row-tile skip; 2 S row+col skip; 3 PV row skip + K clamp;
//       4 final zero-fill padded rows.
#define ASTRH   72
#define ABYTES  (128*ASTRH*2)       // 18432
#define STAGEB  (2*ABYTES)          // 36864
#define SMEM_SZ (3*STAGEB)          // 110592
#define SREG    136

template<int MODE, int SKIP>
__global__ void __launch_bounds__(256, 2)
gemm_mma(const __half* __restrict__ A, long long sA,
         const __half* __restrict__ Bm, long long sB,
         int M, int N, int K,
         void* __restrict__ C, long long sC,
         const float* __restrict__ bias, int sBias,
         const float* __restrict__ resid,
         const __half* B2, const float* bias2, void* C2,
         const __half* B3, const float* bias3, void* C3)
{
    extern __shared__ char dsm[];
    const int tid  = threadIdx.x;
    const int w    = tid >> 5;
    const int lane = tid & 31;
    const int wm   = w & 1;
    const int wn   = w >> 1;
    const int batch = blockIdx.z;
    const int bm = blockIdx.y * 128;

    const __half* Bsrc = Bm;
    const float* biasp = bias;
    void* Cp = C;
    int bn = blockIdx.x * 128;
    int smode = MODE;
    if (MODE == 5) {
        const int bx = blockIdx.x;
        if (bx < 4)      { smode = 0; bn = bx * 128; }
        else if (bx < 8) { smode = 0; bn = (bx-4) * 128; Bsrc = B2; biasp = bias2; Cp = C2; }
        else             { smode = 6; bn = (bx-8) * 128; Bsrc = B3; biasp = bias3; Cp = C3; }
    }

    int Keff = K;
    if (SKIP == 1) {
        if ((bm & (LSEQ-1)) >= g_len[bm >> 10]) return;
    } else if (SKIP == 2) {
        const int L = g_len[batch & (BATCH-1)];
        if (bm >= L || bn >= L) return;
    } else if (SKIP == 3) {
        const int L = g_len[batch & (BATCH-1)];
        if (bm >= L) return;
        Keff = (L + 63) & ~63;
    } else if (SKIP == 4) {
        if ((bm & (LSEQ-1)) >= g_len[bm >> 10]) {
            float* Cf = (float*)Cp;
            const float4 z = {0.f, 0.f, 0.f, 0.f};
            for (int i = tid; i < 128*32; i += 256) {
                const int r = i >> 5, c4 = i & 31;
                *reinterpret_cast<float4*>(&Cf[(long long)(bm + r)*N + bn + c4*4]) = z;
            }
            return;
        }
    }

    const __half* Ab = A    + (long long)batch * sA;
    const __half* Bb = Bsrc + (long long)batch * sB;
    const uint32_t smem0 = smem_u32(dsm);
    const int KC = Keff >> 6;

    auto load_stage = [&](int kc) {
        const int st = kc % 3;
        const uint32_t sa = smem0 + st * STAGEB;
        const uint32_t sb = sa + ABYTES;
        const int k0 = kc << 6;
        #pragma unroll
        for (int i = 0; i < 4; i++) {
            const int idx = tid + i * 256;
            const int row = idx >> 3, chk = idx & 7;
            cp16(sa + row*(ASTRH*2) + chk*16,
                 Ab + (long long)(bm + row) * K + k0 + chk*8);
        }
        #pragma unroll
        for (int i = 0; i < 4; i++) {
            const int idx = tid + i * 256;
            const int row = idx >> 3, chk = idx & 7;
            cp16(sb + row*(ASTRH*2) + chk*16,
                 Bb + (long long)(bn + row) * K + k0 + chk*8);
        }
        asm volatile("cp.async.commit_group;" ::: "memory");
    };

    float acc[4][4][4];
    #pragma unroll
    for (int i = 0; i < 4; i++)
        #pragma unroll
        for (int j = 0; j < 4; j++)
            #pragma unroll
            for (int q = 0; q < 4; q++) acc[i][j][q] = 0.f;

    load_stage(0);
    if (KC > 1) load_stage(1);

    const int lrow_a  = lane & 15;
    const int lkoff_a = (lane >> 4) * 8;
    const int lrow_b  = (lane & 7) + ((lane >> 4) << 3);
    const int lkoff_b = (lane & 8) ? 8 : 0;

    for (int kc = 0; kc < KC; kc++) {
        if (kc + 1 < KC) asm volatile("cp.async.wait_group 1;" ::: "memory");
        else             asm volatile("cp.async.wait_group 0;" ::: "memory");
        __syncthreads();
        if (kc + 2 < KC) load_stage(kc + 2);

        const int st = kc % 3;
        const uint32_t Abase = smem0 + st * STAGEB;
        const uint32_t Bbase = Abase + ABYTES;

        #pragma unroll
        for (int ks = 0; ks < 4; ks++) {
            uint32_t af[4][4];
            #pragma unroll
            for (int mt = 0; mt < 4; mt++) {
                const uint32_t addr = Abase +
                    ((wm*64 + mt*16 + lrow_a)*ASTRH + ks*16 + lkoff_a) * 2;
                ldsm4(af[mt][0], af[mt][1], af[mt][2], af[mt][3], addr);
            }
            uint32_t bf[4][2];
            #pragma unroll
            for (int np = 0; np < 2; np++) {
                const uint32_t addr = Bbase +
                    ((wn*32 + np*16 + lrow_b)*ASTRH + ks*16 + lkoff_b) * 2;
                ldsm4(bf[np*2][0], bf[np*2][1], bf[np*2+1][0], bf[np*2+1][1], addr);
            }
            #pragma unroll
            for (int mt = 0; mt < 4; mt++)
                #pragma unroll
                for (int nt = 0; nt < 4; nt++)
                    mma_f16(acc[mt][nt][0], acc[mt][nt][1], acc[mt][nt][2], acc[mt][nt][3],
                            af[mt][0], af[mt][1], af[mt][2], af[mt][3],
                            bf[nt][0], bf[nt][1]);
        }
    }

    if (MODE == 5 && smode == 6) {   // V transposed store via smem staging
        __syncthreads();
        __half* stg = reinterpret_cast<__half*>(dsm);
        #pragma unroll
        for (int mt = 0; mt < 4; mt++) {
            #pragma unroll
            for (int half_ = 0; half_ < 2; half_++) {
                const int ml = wm*64 + mt*16 + (lane >> 2) + half_*8;
                #pragma unroll
                for (int nt = 0; nt < 4; nt++) {
                    const int nl = wn*32 + nt*8 + (lane & 3)*2;
                    const float2 bv = *reinterpret_cast<const float2*>(&biasp[bn + nl]);
                    stg[nl*SREG + ml]     = __float2half_rn(acc[mt][nt][half_*2 + 0] + bv.x);
                    stg[(nl+1)*SREG + ml] = __float2half_rn(acc[mt][nt][half_*2 + 1] + bv.y);
                }
            }
        }
        __syncthreads();
        const int h = bn >> 9, dv0 = bn & 511;
        const int b = bm >> 10, l0 = bm & (LSEQ-1);
        __half* Vt = (__half*)Cp + (((long long)h*BATCH + b)*DVH + dv0)*LSEQ + l0;
        #pragma unroll
        for (int i = 0; i < 8; i++) {
            const int u = tid + i*256;
            const int dv = u >> 4, lc = u & 15;
            const uint4 o = *reinterpret_cast<const uint4*>(&stg[dv*SREG + lc*8]);
            *reinterpret_cast<uint4*>(&Vt[(long long)dv*LSEQ + lc*8]) = o;
        }
        return;
    }

    #pragma unroll
    for (int mt = 0; mt < 4; mt++) {
        const int r0 = bm + wm*64 + mt*16 + (lane >> 2);
        #pragma unroll
        for (int half_ = 0; half_ < 2; half_++) {
            const int m = r0 + half_*8;
            const int b_idx = m >> 10, l_idx = m & (LSEQ-1);
            #pragma unroll
            for (int nt = 0; nt < 4; nt++) {
                const int n = bn + wn*32 + nt*8 + (lane & 3)*2;
                const float v0 = acc[mt][nt][half_*2 + 0];
                const float v1 = acc[mt][nt][half_*2 + 1];
                if (MODE == 5) {
                    const float2 bv = *reinterpret_cast<const float2*>(&biasp[n]);
                    const int h = n >> 6, d = n & 63;
                    __half* Ch = (__half*)Cp;
                    *reinterpret_cast<__half2*>(&Ch[((long long)h*MTOT + m)*DKH + d]) =
                        __floats2half2_rn(v0 + bv.x, v1 + bv.y);
                } else if (MODE == 7) {   // fp16 plain batched (S, O)
                    __half* Ch = (__half*)Cp;
                    *reinterpret_cast<__half2*>(
                        &Ch[(long long)batch*sC + (long long)m*N + n]) =
                        __floats2half2_rn(v0, v1);
                } else if (MODE == 3) {   // fp16 + per-batch bias (G)
                    const float2 bv = *reinterpret_cast<const float2*>(
                        &biasp[(long long)batch*sBias + n]);
                    __half* Ch = (__half*)Cp;
                    *reinterpret_cast<__half2*>(
                        &Ch[(long long)batch*sC + (long long)m*N + n]) =
                        __floats2half2_rn(v0 + bv.x, v1 + bv.y);
                } else {                  // MODE 4: fp32 final
                    float* Cf = (float*)Cp;
                    float2 o;
                    if (l_idx >= g_len[b_idx]) { o.x = 0.f; o.y = 0.f; }
                    else {
                        const float2 bv = *reinterpret_cast<const float2*>(&biasp[n]);
                        const float2 rv = *reinterpret_cast<const float2*>(
                            &resid[(long long)m*N + n]);
                        o.x = v0 + bv.x + rv.x;
                        o.y = v1 + bv.y + rv.y;
                    }
                    *reinterpret_cast<float2*>(&Cf[(long long)m*N + n]) = o;
                }
            }
        }
    }
}

// ---------------- masked row softmax: fp16 in (S), fp16 out (P) --------------
__global__ void softmax_rows(const __half* __restrict__ S, __half* __restrict__ P) {
    const int hb  = blockIdx.y;
    const int len = g_len[hb & (BATCH-1)];
    const int q   = blockIdx.x;
    if (q >= len) return;                  // padded rows: P stays 0 (zero-init)
    const uint2* row = reinterpret_cast<const uint2*>(
        S + ((long long)hb * LSEQ + q) * LSEQ);
    __half2* prow = reinterpret_cast<__half2*>(
        P + ((long long)hb * LSEQ + q) * LSEQ);

    const int t = threadIdx.x;
    const uint2 u = row[t];
    const float2 va = __half22float2(*reinterpret_cast<const __half2*>(&u.x));
    const float2 vb = __half22float2(*reinterpret_cast<const __half2*>(&u.y));
    const int j0 = t * 4;
    const float NEG = -1e30f;
    float x0 = (j0+0 < len) ? va.x : NEG;
    float x1 = (j0+1 < len) ? va.y : NEG;
    float x2 = (j0+2 < len) ? vb.x : NEG;
    float x3 = (j0+3 < len) ? vb.y : NEG;

    __shared__ float rmax[8], rsum[8];
    float mx = fmaxf(fmaxf(x0, x1), fmaxf(x2, x3));
    #pragma unroll
    for (int o = 16; o; o >>= 1) mx = fmaxf(mx, __shfl_xor_sync(~0u, mx, o));
    if ((t & 31) == 0) rmax[t >> 5] = mx;
    __syncthreads();
    mx = rmax[0];
    #pragma unroll
    for (int i = 1; i < 8; i++) mx = fmaxf(mx, rmax[i]);
    mx *= 0.125f;

    const float e0 = __expf(x0*0.125f - mx);
    const float e1 = __expf(x1*0.125f - mx);
    const float e2 = __expf(x2*0.125f - mx);
    const float e3 = __expf(x3*0.125f - mx);
    float s = e0 + e1 + e2 + e3;
    #pragma unroll
    for (int o = 16; o; o >>= 1) s += __shfl_xor_sync(~0u, s, o);
    if ((t & 31) == 0) rsum[t >> 5] = s;
    __syncthreads();
    s = rsum[0];
    #pragma unroll
    for (int i = 1; i < 8; i++) s += rsum[i];
    const float inv = 1.f / s;

    prow[t*2]   = __floats2half2_rn(e0*inv, e1*inv);
    prow[t*2+1] = __floats2half2_rn(e2*inv, e3*inv);
}

// ---------------- head-gate softmax + weighted combine (fp16 in/out) ---------
__global__ void gate_combine(const __half* __restrict__ G,
                             const __half* __restrict__ O,
                             __half* __restrict__ Y) {
    const int HS4 = MTOT*DVH/4;
    const int i = blockIdx.x * blockDim.x + threadIdx.x;
    if (i >= HS4) return;
    const int m = i >> 7;
    if ((m & (LSEQ-1)) >= g_len[m >> 10]) return;

    const uint2* G4 = reinterpret_cast<const uint2*>(G);
    const uint2* O4 = reinterpret_cast<const uint2*>(O);
    float g[NHEAD][4];
    float mx0 = -1e30f, mx1 = -1e30f, mx2 = -1e30f, mx3 = -1e30f;
    #pragma unroll
    for (int h = 0; h < NHEAD; h++) {
        const uint2 u = G4[(long long)h*HS4 + i];
        const float2 a = __half22float2(*reinterpret_cast<const __half2*>(&u.x));
        const float2 b = __half22float2(*reinterpret_cast<const __half2*>(&u.y));
        g[h][0] = a.x; g[h][1] = a.y; g[h][2] = b.x; g[h][3] = b.y;
        mx0 = fmaxf(mx0, a.x); mx1 = fmaxf(mx1, a.y);
        mx2 = fmaxf(mx2, b.x); mx3 = fmaxf(mx3, b.y);
    }
    float acc0=0, acc1=0, acc2=0, acc3=0, s0=0, s1=0, s2=0, s3=0;
    #pragma unroll
    for (int h = 0; h < NHEAD; h++) {
        const uint2 u = O4[(long long)h*HS4 + i];
        const float2 a = __half22float2(*reinterpret_cast<const __half2*>(&u.x));
        const float2 b = __half22float2(*reinterpret_cast<const __half2*>(&u.y));
        const float e0 = __expf(g[h][0] - mx0), e1 = __expf(g[h][1] - mx1);
        const float e2 = __expf(g[h][2] - mx2), e3 = __expf(g[h][3] - mx3);
        s0 += e0; s1 += e1; s2 += e2; s3 += e3;
        acc0 += e0*a.x; acc1 += e1*a.y; acc2 += e2*b.x; acc3 += e3*b.y;
    }
    uint2 o;
    *reinterpret_cast<__half2*>(&o.x) = __floats2half2_rn(acc0/s0, acc1/s1);
    *reinterpret_cast<__half2*>(&o.y) = __floats2half2_rn(acc2/s2, acc3/s3);
    reinterpret_cast<uint2*>(Y)[i] = o;
}

// ---------------- launch ------------------------------------------------------
extern "C" void kernel_launch(void* const* d_in, const int* in_sizes, int n_in,
                              void* d_out, int out_size) {
    const float*         enc  = (const float*)d_in[0];
    const unsigned char* npm  = (const unsigned char*)d_in[1];
    const float* w_q  = (const float*)d_in[3];
    const float* b_q  = (const float*)d_in[4];
    const float* w_k  = (const float*)d_in[5];
    const float* b_k  = (const float*)d_in[6];
    const float* w_v  = (const float*)d_in[7];
    const float* b_v  = (const float*)d_in[8];
    const float* w_g  = (const float*)d_in[9];
    const float* b_g  = (const float*)d_in[10];
    const float* w_fc = (const float*)d_in[11];
    const float* b_fc = (const float*)d_in[12];
    float* out = (float*)d_out;

    __half *pEnc,*pWq,*pWk,*pWv,*pWg,*pWfc,*pQ,*pK,*pVt,*pS,*pP,*pO,*pG,*pY;
    cudaGetSymbolAddress((void**)&pEnc, g_ench);
    cudaGetSymbolAddress((void**)&pWq,  g_Wqh);
    cudaGetSymbolAddress((void**)&pWk,  g_Wkh);
    cudaGetSymbolAddress((void**)&pWv,  g_Wvh);
    cudaGetSymbolAddress((void**)&pWg,  g_Wgh);
    cudaGetSymbolAddress((void**)&pWfc, g_Wfch);
    cudaGetSymbolAddress((void**)&pQ,   g_Q);
    cudaGetSymbolAddress((void**)&pK,   g_K);
    cudaGetSymbolAddress((void**)&pVt,  g_Vt);
    cudaGetSymbolAddress((void**)&pS,   g_S);
    cudaGetSymbolAddress((void**)&pP,   g_P);
    cudaGetSymbolAddress((void**)&pO,   g_O);
    cudaGetSymbolAddress((void**)&pG,   g_G);
    cudaGetSymbolAddress((void**)&pY,   g_Y);

    cudaFuncSetAttribute(gemm_mma<5,1>, cudaFuncAttributeMaxDynamicSharedMemorySize, SMEM_SZ);
    cudaFuncSetAttribute(gemm_mma<7,2>, cudaFuncAttributeMaxDynamicSharedMemorySize, SMEM_SZ);
    cudaFuncSetAttribute(gemm_mma<7,3>, cudaFuncAttributeMaxDynamicSharedMemorySize, SMEM_SZ);
    cudaFuncSetAttribute(gemm_mma<3,1>, cudaFuncAttributeMaxDynamicSharedMemorySize, SMEM_SZ);
    cudaFuncSetAttribute(gemm_mma<4,4>, cudaFuncAttributeMaxDynamicSharedMemorySize, SMEM_SZ);

    const int M = MTOT;
    dim3 blk(256);

    convert_inputs<<<(N_ENC + 3*N_WQ + 2*N_WV) / 1024, 256>>>(enc, w_q, w_k, w_v, w_g, w_fc);
    prep_mask<<<1, 256>>>(npm);

    // Fused Q/K/V projections (fp16): Q,K -> [h][m][dk]; V -> Vt[h][b][dv][l]
    gemm_mma<5,1><<<dim3(40, M/128, 1), blk, SMEM_SZ>>>(
        pEnc,0, pWq,0, M, NHEAD*DKH, DMODEL, pQ,0, b_q,0, nullptr,
        pWk, b_k, pK, pWv, b_v, pVt);
    // S = Q @ K^T per (h,b), fp16 out, masked tiles skipped
    gemm_mma<7,2><<<dim3(LSEQ/128, LSEQ/128, NHEAD*BATCH), blk, SMEM_SZ>>>(
        pQ,(long long)LSEQ*DKH, pK,(long long)LSEQ*DKH,
        LSEQ, LSEQ, DKH, pS,(long long)LSEQ*LSEQ, nullptr,0, nullptr,
        nullptr,nullptr,nullptr, nullptr,nullptr,nullptr);
    softmax_rows<<<dim3(LSEQ, NHEAD*BATCH), 256>>>(pS, pP);
    // O = P @ Vt^T per (h,b), fp16 out, K clamped to len
    gemm_mma<7,3><<<dim3(DVH/128, LSEQ/128, NHEAD*BATCH), blk, SMEM_SZ>>>(
        pP,(long long)LSEQ*LSEQ, pVt,(long long)DVH*LSEQ,
        LSEQ, DVH, LSEQ, pO,(long long)LSEQ*DVH, nullptr,0, nullptr,
        nullptr,nullptr,nullptr, nullptr,nullptr,nullptr);
    // gate logits: batched over heads, per-head bias, fp16 out
    gemm_mma<3,1><<<dim3(DVH/128, M/128, NHEAD), blk, SMEM_SZ>>>(
        pO,(long long)M*DVH, pWg,(long long)DVH*DMODEL,
        M, DVH, DMODEL, pG,(long long)M*DVH, b_g, DVH, nullptr,
        nullptr,nullptr,nullptr, nullptr,nullptr,nullptr);
    gate_combine<<<(M*DVH/4 + 255)/256, 256>>>(pG, pO, pY);
    // final FC + bias + residual + pad zeroing (fp32 out)
    gemm_mma<4,4><<<dim3(DMODEL/128, M/128, 1), blk, SMEM_SZ>>>(
        pY,0, pWfc,0, M, DMODEL, DVH, out,0, b_fc,0, enc,
        nullptr,nullptr,nullptr, nullptr,nullptr,nullptr);
}